// round 14
// baseline (speedup 1.0000x reference)
#include <cuda_runtime.h>
#include <cuda_fp16.h>
#include <cstdint>

#define BATCH 4096
#define OBS 16
#define TDEC 32
#define H 512
#define NG 2048
#define NSTAGE 8
#define DEPTH 3
#define BM 128
#define BN 128
#define THREADS 256
#define GRID 296
#define NJOBS 1024
#define STAGE_BYTES 32768
#define TILE_BYTES 16384
#define TILE_HALF 8192
#define DYN_SMEM (DEPTH * STAGE_BYTES)   // 98304

// ---------------- device state ----------------
__device__ __align__(16) __half  g_hT[2][2][32][8][TILE_HALF];  // tiled+swizzled h [z][parity][my][stage]
__device__ __align__(16) __half  g_WsT[4][16][8][TILE_HALF];    // tiled+swizzled W [lstm][nx][stage]
__device__ __align__(16) float   g_cF[2][BATCH * H];            // c, fragment-native flat layout
__device__ __align__(16) float   g_hF[2][BATCH * H];            // fp32 h fragments (last enc step)
__device__ __align__(16) float   g_Wi[4][NG * 4];
__device__ __align__(16) float   g_bb[4][NG];
__device__ __align__(16) float   g_ls[BATCH * 4];
__device__ __align__(16) float   g_lp[BATCH * 4];
__device__ unsigned              g_job[64];

// ---------------- helpers ----------------
__device__ __forceinline__ unsigned su32(const void* p) {
    return (unsigned)__cvta_generic_to_shared(p);
}
__device__ __forceinline__ unsigned swz(unsigned o) { return o ^ ((o >> 3) & 0x70); }
__device__ __forceinline__ float sigf(float x) { return 1.f / (1.f + __expf(-x)); }
__device__ __forceinline__ float tanhfast(float x) { return 2.f / (1.f + __expf(-2.f * x)) - 1.f; }

#define BAR_INIT(a, c) asm volatile("mbarrier.init.shared.b64 [%0], %1;" :: "r"(a), "r"(c) : "memory")
#define BAR_EXPECT(a, n) asm volatile("mbarrier.arrive.expect_tx.shared.b64 _, [%0], %1;" :: "r"(a), "r"(n) : "memory")
#define BAR_ARRIVE(a) asm volatile("mbarrier.arrive.shared.b64 _, [%0];" :: "r"(a) : "memory")
#define BAR_WAIT(a, p) do { unsigned d_ = 0; while (!d_) { \
    asm volatile("{\n\t.reg .pred p;\n\t" \
        "mbarrier.try_wait.parity.acquire.cta.shared::cta.b64 p, [%1], %2, 0x989680;\n\t" \
        "selp.b32 %0, 1, 0, p;\n\t}" : "=r"(d_) : "r"(a), "r"(p) : "memory"); } } while (0)

__device__ __forceinline__ void bulkcp(unsigned dst, const void* src, unsigned bytes, unsigned mbar) {
    asm volatile("cp.async.bulk.shared::cluster.global.mbarrier::complete_tx::bytes [%0], [%1], %2, [%3];"
        :: "r"(dst), "l"(src), "r"(bytes), "r"(mbar) : "memory");
}

// ---------------- weight prep: permute + tile + swizzle ----------------
struct WPtrs { const float* Wh[4]; const float* Wi[4]; const float* bb[4]; };

__global__ void prep_weights(WPtrs p) {
    int k = threadIdx.x, j = blockIdx.x, l = blockIdx.y;
    float w = p.Wh[l][j * H + k];
    int pr = 4 * (j & (H - 1)) + (j >> 9);   // 4u + gate
    int nx = pr >> 7, r = pr & 127;
    int sp = k >> 6, c = k & 63;
    char* tb = (char*)g_WsT[l][nx][sp];
    *(__half*)(tb + swz((unsigned)(r * 128 + c * 2))) = __float2half(w);
    if (k < 4)  g_Wi[l][pr * 4 + k] = p.Wi[l][j * 4 + k];
    if (k == 0) g_bb[l][pr] = p.bb[l][j];
}

__global__ void init_state(const float* speed, const float* pos) {
    int idx = blockIdx.x * blockDim.x + threadIdx.x;
    if (idx < 2 * BATCH * H) {
        int s = idx / (BATCH * H), i = idx % (BATCH * H);
        ((__half*)g_hT[s][0])[i] = __float2half(0.f);
        ((float*)g_cF)[idx] = 0.f;
    }
    if (idx < BATCH * 4) {
        int b = idx >> 2, k = idx & 3;
        g_ls[idx] = speed[b * (OBS * 4) + (OBS - 1) * 4 + k];
        g_lp[idx] = pos[b * (OBS * 4) + (OBS - 1) * 4 + k];
    }
    if (idx < 64) g_job[idx] = 0;
}

// combine: c_s = c0+c1 (flat, both slabs); h_s = h0+h1 -> parity-0 tiles (both slabs)
__global__ void combine_state() {
    int i = blockIdx.x * blockDim.x + threadIdx.x;   // 0 .. BATCH*H-1 (fragment flat index)
    float cs = g_cF[0][i] + g_cF[1][i];
    g_cF[0][i] = cs; g_cF[1][i] = cs;
    float hs = g_hF[0][i] + g_hF[1][i];
    // decode fragment index -> (m, u)
    int q = i & 15, tid = (i >> 4) & 255, job = i >> 12;
    int im = q >> 2, g = q & 3;
    int warp = tid >> 5, lane = tid & 31, c4 = lane & 3;
    int nx = job & 15, my = job >> 4;
    int rml = (warp & 1) * 64 + im * 16 + (lane >> 2) + 8 * (c4 & 1);
    int u = nx * 32 + (warp >> 1) * 8 + 2 * g + (c4 >> 1);
    __half hv = __float2half(hs);
    unsigned off = swz((unsigned)(rml * 128 + (u & 63) * 2));
    *(__half*)((char*)g_hT[0][0][my][u >> 6] + off) = hv;
    *(__half*)((char*)g_hT[1][0][my][u >> 6] + off) = hv;
}

// ---------------- fused LSTM cell: persistent, cross-job pipelined, shuffle epilogue ----------------
__global__ void __launch_bounds__(THREADS, 2) lstm_cell(
    int lstm_base, const float* x0, const float* x1, int xstride, int internal_x,
    int rp, int jid, int write_h32)
{
    extern __shared__ char smem[];
    __shared__ float sB[BN];
    __shared__ float sWi[BN * 4];
    __shared__ int s_job[2];
    __shared__ __align__(8) uint64_t s_full[DEPTH];
    __shared__ __align__(8) uint64_t s_empty[DEPTH];

    const int tid = threadIdx.x;
    const int lane = tid & 31, warp = tid >> 5;
    const int c4 = lane & 3;
    const int wmb = (warp & 1) * 64;
    const int wnb = (warp >> 1) * 32;
    const int wp = 1 - rp;

    if (tid < DEPTH) {
        BAR_INIT(su32(&s_full[tid]), 1u);
        BAR_INIT(su32(&s_empty[tid]), 8u);
    }

    const char* curA = nullptr; const char* curB = nullptr;
    const char* nxtA = nullptr; const char* nxtB = nullptr;
    int nj = NJOBS;

    if (tid == 0) {
        int j = (int)atomicAdd(&g_job[jid], 1u);
        s_job[0] = j;
        if (j < NJOBS) {
            int jnx = j & 15, jmy = (j >> 4) & 31, jz = j >> 9;
            curA = (const char*)g_hT[jz][rp][jmy];
            curB = (const char*)g_WsT[lstm_base + jz][jnx];
            #pragma unroll
            for (int gsp = 0; gsp < DEPTH; gsp++) {
                unsigned mb = su32(&s_full[gsp]);
                unsigned dst = su32(smem + gsp * STAGE_BYTES);
                BAR_EXPECT(mb, (unsigned)STAGE_BYTES);
                bulkcp(dst,              curA + gsp * TILE_BYTES, TILE_BYTES, mb);
                bulkcp(dst + TILE_BYTES, curB + gsp * TILE_BYTES, TILE_BYTES, mb);
            }
        }
    }
    __syncthreads();

    for (int it = 0;; it++) {
        const int job = s_job[it & 1];
        if (job >= NJOBS) break;
        const int nx = job & 15, my = (job >> 4) & 31, z = job >> 9;
        const int lstm = lstm_base + z;

        if (tid < BN) {
            int n = nx * BN + tid;
            sB[tid] = g_bb[lstm][n];
            #pragma unroll
            for (int k = 0; k < 4; k++) sWi[tid * 4 + k] = g_Wi[lstm][n * 4 + k];
        }
        __syncthreads();

        float acc[4][4][4] = {};
        const int gs0 = it * 8;

        for (int s = 0; s < NSTAGE; s++) {
            const int gs = gs0 + s;
            BAR_WAIT(su32(&s_full[gs % 3]), (unsigned)((gs / 3) & 1));

            const char* Ab = smem + (gs % 3) * STAGE_BYTES;
            const char* Bb = Ab + TILE_BYTES;
            #pragma unroll
            for (int kk = 0; kk < 4; kk++) {
                uint32_t a[4][4];
                #pragma unroll
                for (int im = 0; im < 4; im++) {
                    int row = wmb + im * 16 + (lane & 15);
                    unsigned off = swz(row * 128 + kk * 32 + ((lane >> 4) << 4));
                    asm volatile("ldmatrix.sync.aligned.m8n8.x4.shared.b16 {%0,%1,%2,%3}, [%4];"
                        : "=r"(a[im][0]), "=r"(a[im][1]), "=r"(a[im][2]), "=r"(a[im][3])
                        : "r"(su32(Ab + off)));
                }
                uint32_t b[4][2];
                #pragma unroll
                for (int gp = 0; gp < 2; gp++) {
                    int row = wnb + gp * 16 + ((lane >> 4) << 3) + (lane & 7);
                    unsigned off = swz(row * 128 + kk * 32 + (((lane >> 3) & 1) << 4));
                    asm volatile("ldmatrix.sync.aligned.m8n8.x4.shared.b16 {%0,%1,%2,%3}, [%4];"
                        : "=r"(b[2 * gp][0]), "=r"(b[2 * gp][1]),
                          "=r"(b[2 * gp + 1][0]), "=r"(b[2 * gp + 1][1])
                        : "r"(su32(Bb + off)));
                }
                #pragma unroll
                for (int im = 0; im < 4; im++)
                    #pragma unroll
                    for (int g = 0; g < 4; g++)
                        asm volatile("mma.sync.aligned.m16n8k16.row.col.f32.f16.f16.f32 "
                            "{%0,%1,%2,%3}, {%4,%5,%6,%7}, {%8,%9}, {%0,%1,%2,%3};"
                            : "+f"(acc[im][g][0]), "+f"(acc[im][g][1]),
                              "+f"(acc[im][g][2]), "+f"(acc[im][g][3])
                            : "r"(a[im][0]), "r"(a[im][1]), "r"(a[im][2]), "r"(a[im][3]),
                              "r"(b[g][0]), "r"(b[g][1]));
            }

            if (lane == 0) BAR_ARRIVE(su32(&s_empty[gs % 3]));

            if (tid == 0) {
                if (s == 5) {   // fetch next job; publish coords
                    nj = (int)atomicAdd(&g_job[jid], 1u);
                    s_job[(it + 1) & 1] = nj;
                    if (nj < NJOBS) {
                        int nnx = nj & 15, nmy = (nj >> 4) & 31, nz = nj >> 9;
                        nxtA = (const char*)g_hT[nz][rp][nmy];
                        nxtB = (const char*)g_WsT[lstm_base + nz][nnx];
                    }
                }
                const int tgs = gs + 3;
                const char* A_; const char* B_; int stg; bool valid;
                if (s < 5) { valid = true; A_ = curA; B_ = curB; stg = s + 3; }
                else       { valid = (nj < NJOBS); A_ = nxtA; B_ = nxtB; stg = s - 5; }
                if (valid) {
                    BAR_WAIT(su32(&s_empty[tgs % 3]), (unsigned)(((tgs / 3) - 1) & 1));
                    unsigned mb = su32(&s_full[tgs % 3]);
                    unsigned dst = su32(smem + (tgs % 3) * STAGE_BYTES);
                    BAR_EXPECT(mb, (unsigned)STAGE_BYTES);
                    bulkcp(dst,              A_ + stg * TILE_BYTES, TILE_BYTES, mb);
                    bulkcp(dst + TILE_BYTES, B_ + stg * TILE_BYTES, TILE_BYTES, mb);
                }
            }
        }
        if (tid == 0 && nj < NJOBS) { curA = nxtA; curB = nxtB; }

        // ---------------- shuffle epilogue (no smem) ----------------
        {
            const float* xbase = internal_x ? (z ? g_lp : g_ls) : (z ? x1 : x0);
            float* cslab = g_cF[z];
            float* hslab = g_hF[z];
            char* hTw = (char*)g_hT[z][wp][my][nx >> 1];
            const size_t cbase = ((size_t)((my * 16 + nx) * 256 + tid)) * 16;

            #pragma unroll
            for (int im = 0; im < 4; im++) {
                const int rml = wmb + im * 16 + (lane >> 2) + 8 * (c4 & 1);
                const float4 xv = *(const float4*)(xbase + (size_t)(my * 128 + rml) * xstride);
                float4 coldv = *(const float4*)&cslab[cbase + im * 4];
                float cold[4] = { coldv.x, coldv.y, coldv.z, coldv.w };
                float cn[4], hn[4];
                #pragma unroll
                for (int g = 0; g < 4; g++) {
                    float s0 = (c4 & 1) ? acc[im][g][0] : acc[im][g][2];
                    float s1 = (c4 & 1) ? acc[im][g][1] : acc[im][g][3];
                    float r0 = __shfl_xor_sync(0xffffffffu, s0, 1);
                    float r1 = __shfl_xor_sync(0xffffffffu, s1, 1);
                    float q0, q1, q2, q3;
                    if ((c4 & 1) == 0) { q0 = acc[im][g][0]; q1 = acc[im][g][1]; q2 = r0; q3 = r1; }
                    else               { q0 = r0; q1 = r1; q2 = acc[im][g][2]; q3 = acc[im][g][3]; }
                    const int ucta = (warp >> 1) * 8 + 2 * g + (c4 >> 1);
                    const int nn = ucta * 4;
                    const float4 bv = *(const float4*)&sB[nn];
                    const float4 w0 = *(const float4*)&sWi[(nn + 0) * 4];
                    const float4 w1 = *(const float4*)&sWi[(nn + 1) * 4];
                    const float4 w2 = *(const float4*)&sWi[(nn + 2) * 4];
                    const float4 w3 = *(const float4*)&sWi[(nn + 3) * 4];
                    float g0 = q0 + bv.x + xv.x * w0.x + xv.y * w0.y + xv.z * w0.z + xv.w * w0.w;
                    float g1 = q1 + bv.y + xv.x * w1.x + xv.y * w1.y + xv.z * w1.z + xv.w * w1.w;
                    float g2 = q2 + bv.z + xv.x * w2.x + xv.y * w2.y + xv.z * w2.z + xv.w * w2.w;
                    float g3 = q3 + bv.w + xv.x * w3.x + xv.y * w3.y + xv.z * w3.z + xv.w * w3.w;
                    float iv = sigf(g0);
                    float fv = sigf(g1);
                    float gg = tanhfast(g2);
                    float ov = sigf(g3);
                    float cnv = fv * cold[g] + iv * gg;
                    cn[g] = cnv;
                    hn[g] = ov * tanhfast(cnv);
                }
                *(float4*)&cslab[cbase + im * 4] = make_float4(cn[0], cn[1], cn[2], cn[3]);
                if (write_h32)
                    *(float4*)&hslab[cbase + im * 4] = make_float4(hn[0], hn[1], hn[2], hn[3]);

                __half2 h01 = __floats2half2_rn(hn[0], hn[1]);
                __half2 h23 = __floats2half2_rn(hn[2], hn[3]);
                unsigned b01 = *(unsigned*)&h01, b23 = *(unsigned*)&h23;
                unsigned send = (c4 >> 1) ? b01 : b23;
                unsigned recv = __shfl_xor_sync(0xffffffffu, send, 2);
                uint2 st;
                if ((c4 >> 1) == 0) {
                    st.x = (b01 & 0xffffu) | (recv << 16);
                    st.y = (b01 >> 16) | (recv & 0xffff0000u);
                } else {
                    st.x = (recv & 0xffffu) | (b23 << 16);
                    st.y = (recv >> 16) | (b23 & 0xffff0000u);
                }
                unsigned bb = (unsigned)(rml * 128 + (nx & 1) * 64 + (warp >> 1) * 16 + (c4 >> 1) * 8);
                *(uint2*)(hTw + swz(bb)) = st;
            }
        }
        __syncthreads();   // publish s_job for next iteration; protect sB/sWi reload
    }
}

// ---------------- decoder projections + feedback (1 wave: 128 CTAs x 32 warps) ----------------
__global__ void __launch_bounds__(1024) proj_kernel(
    const float* W_fs, const float* b_fs,
    const float* W_fc, const float* b_fc,
    const float* W_emb, const float* b_emb,
    float* out, int t, int par)
{
    int warp = threadIdx.x >> 5, lane = threadIdx.x & 31;
    int b = blockIdx.x * 32 + warp;
    float a0 = 0, a1 = 0, a2 = 0, a3 = 0, a4 = 0, a5 = 0;
    unsigned off = swz((unsigned)((b & 127) * 128 + lane * 4));
    #pragma unroll
    for (int sp = 0; sp < 8; sp++) {
        float2 vs = __half22float2(*(const __half2*)((const char*)g_hT[0][par][b >> 7][sp] + off));
        float2 vi = __half22float2(*(const __half2*)((const char*)g_hT[1][par][b >> 7][sp] + off));
        int k = sp * 64 + lane * 2;
        a0 += vs.x * W_fs[k]         + vs.y * W_fs[k + 1];
        a1 += vs.x * W_fs[H + k]     + vs.y * W_fs[H + k + 1];
        a2 += vs.x * W_fs[2 * H + k] + vs.y * W_fs[2 * H + k + 1];
        a3 += vs.x * W_fs[3 * H + k] + vs.y * W_fs[3 * H + k + 1];
        a4 += vi.x * W_fc[k]         + vi.y * W_fc[k + 1];
        a5 += vi.x * W_fc[H + k]     + vi.y * W_fc[H + k + 1];
    }
    #pragma unroll
    for (int o = 16; o; o >>= 1) {
        a0 += __shfl_down_sync(0xffffffffu, a0, o);
        a1 += __shfl_down_sync(0xffffffffu, a1, o);
        a2 += __shfl_down_sync(0xffffffffu, a2, o);
        a3 += __shfl_down_sync(0xffffffffu, a3, o);
        a4 += __shfl_down_sync(0xffffffffu, a4, o);
        a5 += __shfl_down_sync(0xffffffffu, a5, o);
    }
    if (lane == 0) {
        float4 spv;
        spv.x = fminf(fmaxf(a0 + b_fs[0], -100.f), 100.f);
        spv.y = fminf(fmaxf(a1 + b_fs[1], -100.f), 100.f);
        spv.z = fminf(fmaxf(a2 + b_fs[2], -100.f), 100.f);
        spv.w = fminf(fmaxf(a3 + b_fs[3], -100.f), 100.f);
        float it0 = fmaxf(a4 + b_fc[0], 0.f);
        float it1 = fmaxf(a5 + b_fc[1], 0.f);
        *(float4*)&out[((size_t)b * TDEC + t) * 4] = spv;
        *(float4*)&g_ls[b * 4] = spv;
        float4 lpv;
        lpv.x = fmaxf(W_emb[0] * it0 + W_emb[1] * it1 + b_emb[0], 0.f);
        lpv.y = fmaxf(W_emb[2] * it0 + W_emb[3] * it1 + b_emb[1], 0.f);
        lpv.z = fmaxf(W_emb[4] * it0 + W_emb[5] * it1 + b_emb[2], 0.f);
        lpv.w = fmaxf(W_emb[6] * it0 + W_emb[7] * it1 + b_emb[3], 0.f);
        *(float4*)&g_lp[b * 4] = lpv;
        if (t == TDEC - 1) {
            float mx = fmaxf(it0, it1);
            float e0 = expf(it0 - mx), e1 = expf(it1 - mx);
            float s = e0 + e1;
            out[(size_t)BATCH * TDEC * 4 + b * 2]     = e0 / s;
            out[(size_t)BATCH * TDEC * 4 + b * 2 + 1] = e1 / s;
        }
    }
}

// ---------------- launch ----------------
extern "C" void kernel_launch(void* const* d_in, const int* in_sizes, int n_in,
                              void* d_out, int out_size)
{
    const float* speed = (const float*)d_in[0];
    const float* pos   = (const float*)d_in[1];
    WPtrs wpt;
    wpt.Wi[0] = (const float*)d_in[2];  wpt.Wh[0] = (const float*)d_in[3];  wpt.bb[0] = (const float*)d_in[4];
    wpt.Wi[1] = (const float*)d_in[5];  wpt.Wh[1] = (const float*)d_in[6];  wpt.bb[1] = (const float*)d_in[7];
    wpt.Wi[2] = (const float*)d_in[8];  wpt.Wh[2] = (const float*)d_in[9];  wpt.bb[2] = (const float*)d_in[10];
    wpt.Wi[3] = (const float*)d_in[11]; wpt.Wh[3] = (const float*)d_in[12]; wpt.bb[3] = (const float*)d_in[13];
    const float* W_fs  = (const float*)d_in[14];
    const float* b_fs  = (const float*)d_in[15];
    const float* W_fc  = (const float*)d_in[16];
    const float* b_fc  = (const float*)d_in[17];
    const float* W_emb = (const float*)d_in[18];
    const float* b_emb = (const float*)d_in[19];
    float* out = (float*)d_out;

    cudaFuncSetAttribute(lstm_cell, cudaFuncAttributeMaxDynamicSharedMemorySize, DYN_SMEM);

    prep_weights<<<dim3(NG, 4), 512>>>(wpt);
    init_state<<<(2 * BATCH * H + 255) / 256, 256>>>(speed, pos);

    for (int t = 0; t < OBS; t++)
        lstm_cell<<<GRID, THREADS, DYN_SMEM>>>(0, speed + t * 4, pos + t * 4, OBS * 4, 0,
                                               t & 1, t, t == OBS - 1 ? 1 : 0);

    combine_state<<<(BATCH * H + 255) / 256, 256>>>();

    for (int t = 0; t < TDEC; t++) {
        lstm_cell<<<GRID, THREADS, DYN_SMEM>>>(2, nullptr, nullptr, 4, 1, t & 1, 16 + t, 0);
        proj_kernel<<<BATCH / 32, 1024>>>(W_fs, b_fs, W_fc, b_fc, W_emb, b_emb, out, t, 1 - (t & 1));
    }
}

// round 16
// speedup vs baseline: 1.1903x; 1.1903x over previous
#include <cuda_runtime.h>
#include <cuda_fp16.h>
#include <cstdint>

#define BATCH 4096
#define OBS 16
#define TDEC 32
#define H 512
#define NG 2048
#define NSTAGE 8
#define DEPTH 3
#define BM 128
#define BN 128
#define THREADS 256
#define STAGE_BYTES 32768
#define TILE_BYTES 16384
#define TILE_HALF 8192
#define DYN_SMEM (DEPTH * STAGE_BYTES)   // 98304

// ---------------- device state ----------------
__device__ __align__(16) __half  g_hT[2][2][32][8][TILE_HALF];  // tiled+swizzled h [z][parity][my][stage]
__device__ __align__(16) __half  g_WsT[4][16][8][TILE_HALF];    // tiled+swizzled W [lstm][nx][stage]
__device__ __align__(16) float   g_cF[2][BATCH * H];            // c, fragment-native flat layout
__device__ __align__(16) float   g_hF[2][BATCH * H];            // fp32 h fragments (last enc step)
__device__ __align__(16) float   g_Wi[4][NG * 4];
__device__ __align__(16) float   g_bb[4][NG];
__device__ __align__(16) float   g_ls[BATCH * 4];
__device__ __align__(16) float   g_lp[BATCH * 4];

// ---------------- helpers ----------------
__device__ __forceinline__ unsigned su32(const void* p) {
    return (unsigned)__cvta_generic_to_shared(p);
}
__device__ __forceinline__ unsigned swz(unsigned o) { return o ^ ((o >> 3) & 0x70); }
__device__ __forceinline__ float sigf(float x) { return 1.f / (1.f + __expf(-x)); }
__device__ __forceinline__ float tanhfast(float x) { return 2.f / (1.f + __expf(-2.f * x)) - 1.f; }

#define BAR_INIT(a, c) asm volatile("mbarrier.init.shared.b64 [%0], %1;" :: "r"(a), "r"(c) : "memory")
#define BAR_EXPECT(a, n) asm volatile("mbarrier.arrive.expect_tx.shared.b64 _, [%0], %1;" :: "r"(a), "r"(n) : "memory")
#define BAR_WAIT(a, p) do { unsigned d_ = 0; while (!d_) { \
    asm volatile("{\n\t.reg .pred p;\n\t" \
        "mbarrier.try_wait.parity.acquire.cta.shared::cta.b64 p, [%1], %2, 0x989680;\n\t" \
        "selp.b32 %0, 1, 0, p;\n\t}" : "=r"(d_) : "r"(a), "r"(p) : "memory"); } } while (0)

__device__ __forceinline__ void bulkcp(unsigned dst, const void* src, unsigned bytes, unsigned mbar) {
    asm volatile("cp.async.bulk.shared::cluster.global.mbarrier::complete_tx::bytes [%0], [%1], %2, [%3];"
        :: "r"(dst), "l"(src), "r"(bytes), "r"(mbar) : "memory");
}

// ---------------- weight prep: permute + tile + swizzle ----------------
struct WPtrs { const float* Wh[4]; const float* Wi[4]; const float* bb[4]; };

__global__ void prep_weights(WPtrs p) {
    int k = threadIdx.x, j = blockIdx.x, l = blockIdx.y;
    float w = p.Wh[l][j * H + k];
    int pr = 4 * (j & (H - 1)) + (j >> 9);   // 4u + gate
    int nx = pr >> 7, r = pr & 127;
    int sp = k >> 6, c = k & 63;
    char* tb = (char*)g_WsT[l][nx][sp];
    *(__half*)(tb + swz((unsigned)(r * 128 + c * 2))) = __float2half(w);
    if (k < 4)  g_Wi[l][pr * 4 + k] = p.Wi[l][j * 4 + k];
    if (k == 0) g_bb[l][pr] = p.bb[l][j];
}

__global__ void init_state(const float* speed, const float* pos) {
    int idx = blockIdx.x * blockDim.x + threadIdx.x;
    if (idx < 2 * BATCH * H) {
        int s = idx / (BATCH * H), i = idx % (BATCH * H);
        ((__half*)g_hT[s][0])[i] = __float2half(0.f);
        ((float*)g_cF)[idx] = 0.f;
    }
    if (idx < BATCH * 4) {
        int b = idx >> 2, k = idx & 3;
        g_ls[idx] = speed[b * (OBS * 4) + (OBS - 1) * 4 + k];
        g_lp[idx] = pos[b * (OBS * 4) + (OBS - 1) * 4 + k];
    }
}

// combine: c_s = c0+c1 (flat, both slabs); h_s = h0+h1 -> parity-0 tiles (both slabs)
__global__ void combine_state() {
    int i = blockIdx.x * blockDim.x + threadIdx.x;   // fragment flat index
    float cs = g_cF[0][i] + g_cF[1][i];
    g_cF[0][i] = cs; g_cF[1][i] = cs;
    float hs = g_hF[0][i] + g_hF[1][i];
    int q = i & 15, tid = (i >> 4) & 255, job = i >> 12;
    int im = q >> 2, g = q & 3;
    int warp = tid >> 5, lane = tid & 31, c4 = lane & 3;
    int nx = job & 15, my = job >> 4;
    int rml = (warp & 1) * 64 + im * 16 + (lane >> 2) + 8 * (c4 & 1);
    int u = nx * 32 + (warp >> 1) * 8 + 2 * g + (c4 >> 1);
    __half hv = __float2half(hs);
    unsigned off = swz((unsigned)(rml * 128 + (u & 63) * 2));
    *(__half*)((char*)g_hT[0][0][my][u >> 6] + off) = hv;
    *(__half*)((char*)g_hT[1][0][my][u >> 6] + off) = hv;
}

// ---------------- fused LSTM cell: bulk-copy pipeline + fp16 mma.sync + shuffle epilogue ----------------
__global__ void __launch_bounds__(THREADS, 2) lstm_cell(
    int lstm_base, const float* x0, const float* x1, int xstride, int internal_x,
    int rp, int write_h32)
{
    extern __shared__ char smem[];
    __shared__ float sB[BN];
    __shared__ float sWi[BN * 4];
    __shared__ __align__(8) uint64_t s_full[DEPTH];

    const int z = blockIdx.z;
    const int nx = blockIdx.x;
    const int my = blockIdx.y;
    const int lstm = lstm_base + z;
    const int wp = 1 - rp;
    const int tid = threadIdx.x;
    const int lane = tid & 31, warp = tid >> 5;
    const int c4 = lane & 3;
    const int wmb = (warp & 1) * 64;
    const int wnb = (warp >> 1) * 32;

    const char* Asrc = (const char*)g_hT[z][rp][my];
    const char* Bsrc = (const char*)g_WsT[lstm][nx];

    if (tid < DEPTH) BAR_INIT(su32(&s_full[tid]), 1u);
    if (tid < BN) {
        int n = nx * BN + tid;
        sB[tid] = g_bb[lstm][n];
        #pragma unroll
        for (int k = 0; k < 4; k++) sWi[tid * 4 + k] = g_Wi[lstm][n * 4 + k];
    }
    __syncthreads();

    auto produce = [&](int sp) {
        int sl = sp % DEPTH;
        unsigned mb = su32(&s_full[sl]);
        unsigned dst = su32(smem + sl * STAGE_BYTES);
        BAR_EXPECT(mb, (unsigned)STAGE_BYTES);
        bulkcp(dst,              Asrc + sp * TILE_BYTES, TILE_BYTES, mb);
        bulkcp(dst + TILE_BYTES, Bsrc + sp * TILE_BYTES, TILE_BYTES, mb);
    };

    if (tid == 0) { produce(0); produce(1); produce(2); }

    float acc[4][4][4] = {};

    for (int s = 0; s < NSTAGE; s++) {
        BAR_WAIT(su32(&s_full[s % DEPTH]), (unsigned)((s / DEPTH) & 1));

        const char* Ab = smem + (s % DEPTH) * STAGE_BYTES;
        const char* Bb = Ab + TILE_BYTES;
        #pragma unroll
        for (int kk = 0; kk < 4; kk++) {
            uint32_t a[4][4];
            #pragma unroll
            for (int im = 0; im < 4; im++) {
                int row = wmb + im * 16 + (lane & 15);
                unsigned off = swz(row * 128 + kk * 32 + ((lane >> 4) << 4));
                asm volatile("ldmatrix.sync.aligned.m8n8.x4.shared.b16 {%0,%1,%2,%3}, [%4];"
                    : "=r"(a[im][0]), "=r"(a[im][1]), "=r"(a[im][2]), "=r"(a[im][3])
                    : "r"(su32(Ab + off)));
            }
            uint32_t b[4][2];
            #pragma unroll
            for (int gp = 0; gp < 2; gp++) {
                int row = wnb + gp * 16 + ((lane >> 4) << 3) + (lane & 7);
                unsigned off = swz(row * 128 + kk * 32 + (((lane >> 3) & 1) << 4));
                asm volatile("ldmatrix.sync.aligned.m8n8.x4.shared.b16 {%0,%1,%2,%3}, [%4];"
                    : "=r"(b[2 * gp][0]), "=r"(b[2 * gp][1]),
                      "=r"(b[2 * gp + 1][0]), "=r"(b[2 * gp + 1][1])
                    : "r"(su32(Bb + off)));
            }
            #pragma unroll
            for (int im = 0; im < 4; im++)
                #pragma unroll
                for (int g = 0; g < 4; g++)
                    asm volatile("mma.sync.aligned.m16n8k16.row.col.f32.f16.f16.f32 "
                        "{%0,%1,%2,%3}, {%4,%5,%6,%7}, {%8,%9}, {%0,%1,%2,%3};"
                        : "+f"(acc[im][g][0]), "+f"(acc[im][g][1]),
                          "+f"(acc[im][g][2]), "+f"(acc[im][g][3])
                        : "r"(a[im][0]), "r"(a[im][1]), "r"(a[im][2]), "r"(a[im][3]),
                          "r"(b[g][0]), "r"(b[g][1]));
        }

        __syncthreads();
        if (tid == 0 && s + DEPTH < NSTAGE) produce(s + DEPTH);
    }

    // ---------------- shuffle epilogue (register-only; no smem, no extra barriers) ----------------
    {
        const float* xbase = internal_x ? (z ? g_lp : g_ls) : (z ? x1 : x0);
        float* cslab = g_cF[z];
        float* hslab = g_hF[z];
        char* hTw = (char*)g_hT[z][wp][my][nx >> 1];
        const size_t cbase = ((size_t)((my * 16 + nx) * 256 + tid)) * 16;

        #pragma unroll
        for (int im = 0; im < 4; im++) {
            const int rml = wmb + im * 16 + (lane >> 2) + 8 * (c4 & 1);
            const float4 xv = *(const float4*)(xbase + (size_t)(my * 128 + rml) * xstride);
            float4 coldv = *(const float4*)&cslab[cbase + im * 4];
            float cold[4] = { coldv.x, coldv.y, coldv.z, coldv.w };
            float cn[4], hn[4];
            #pragma unroll
            for (int g = 0; g < 4; g++) {
                float s0 = (c4 & 1) ? acc[im][g][0] : acc[im][g][2];
                float s1 = (c4 & 1) ? acc[im][g][1] : acc[im][g][3];
                float r0 = __shfl_xor_sync(0xffffffffu, s0, 1);
                float r1 = __shfl_xor_sync(0xffffffffu, s1, 1);
                float q0, q1, q2, q3;
                if ((c4 & 1) == 0) { q0 = acc[im][g][0]; q1 = acc[im][g][1]; q2 = r0; q3 = r1; }
                else               { q0 = r0; q1 = r1; q2 = acc[im][g][2]; q3 = acc[im][g][3]; }
                const int ucta = (warp >> 1) * 8 + 2 * g + (c4 >> 1);
                const int nn = ucta * 4;
                const float4 bv = *(const float4*)&sB[nn];
                const float4 w0 = *(const float4*)&sWi[(nn + 0) * 4];
                const float4 w1 = *(const float4*)&sWi[(nn + 1) * 4];
                const float4 w2 = *(const float4*)&sWi[(nn + 2) * 4];
                const float4 w3 = *(const float4*)&sWi[(nn + 3) * 4];
                float g0 = q0 + bv.x + xv.x * w0.x + xv.y * w0.y + xv.z * w0.z + xv.w * w0.w;
                float g1 = q1 + bv.y + xv.x * w1.x + xv.y * w1.y + xv.z * w1.z + xv.w * w1.w;
                float g2 = q2 + bv.z + xv.x * w2.x + xv.y * w2.y + xv.z * w2.z + xv.w * w2.w;
                float g3 = q3 + bv.w + xv.x * w3.x + xv.y * w3.y + xv.z * w3.z + xv.w * w3.w;
                float iv = sigf(g0);
                float fv = sigf(g1);
                float gg = tanhfast(g2);
                float ov = sigf(g3);
                float cnv = fv * cold[g] + iv * gg;
                cn[g] = cnv;
                hn[g] = ov * tanhfast(cnv);
            }
            *(float4*)&cslab[cbase + im * 4] = make_float4(cn[0], cn[1], cn[2], cn[3]);
            if (write_h32)
                *(float4*)&hslab[cbase + im * 4] = make_float4(hn[0], hn[1], hn[2], hn[3]);

            __half2 h01 = __floats2half2_rn(hn[0], hn[1]);
            __half2 h23 = __floats2half2_rn(hn[2], hn[3]);
            unsigned b01 = *(unsigned*)&h01, b23 = *(unsigned*)&h23;
            unsigned send = (c4 >> 1) ? b01 : b23;
            unsigned recv = __shfl_xor_sync(0xffffffffu, send, 2);
            uint2 st;
            if ((c4 >> 1) == 0) {
                st.x = (b01 & 0xffffu) | (recv << 16);
                st.y = (b01 >> 16) | (recv & 0xffff0000u);
            } else {
                st.x = (recv & 0xffffu) | (b23 << 16);
                st.y = (recv >> 16) | (b23 & 0xffff0000u);
            }
            unsigned bb = (unsigned)(rml * 128 + (nx & 1) * 64 + (warp >> 1) * 16 + (c4 >> 1) * 8);
            *(uint2*)(hTw + swz(bb)) = st;
        }
    }
}

// ---------------- decoder projections + feedback (1 wave: 128 CTAs x 32 warps) ----------------
__global__ void __launch_bounds__(1024) proj_kernel(
    const float* W_fs, const float* b_fs,
    const float* W_fc, const float* b_fc,
    const float* W_emb, const float* b_emb,
    float* out, int t, int par)
{
    int warp = threadIdx.x >> 5, lane = threadIdx.x & 31;
    int b = blockIdx.x * 32 + warp;
    float a0 = 0, a1 = 0, a2 = 0, a3 = 0, a4 = 0, a5 = 0;
    unsigned off = swz((unsigned)((b & 127) * 128 + lane * 4));
    #pragma unroll
    for (int sp = 0; sp < 8; sp++) {
        float2 vs = __half22float2(*(const __half2*)((const char*)g_hT[0][par][b >> 7][sp] + off));
        float2 vi = __half22float2(*(const __half2*)((const char*)g_hT[1][par][b >> 7][sp] + off));
        int k = sp * 64 + lane * 2;
        a0 += vs.x * W_fs[k]         + vs.y * W_fs[k + 1];
        a1 += vs.x * W_fs[H + k]     + vs.y * W_fs[H + k + 1];
        a2 += vs.x * W_fs[2 * H + k] + vs.y * W_fs[2 * H + k + 1];
        a3 += vs.x * W_fs[3 * H + k] + vs.y * W_fs[3 * H + k + 1];
        a4 += vi.x * W_fc[k]         + vi.y * W_fc[k + 1];
        a5 += vi.x * W_fc[H + k]     + vi.y * W_fc[H + k + 1];
    }
    #pragma unroll
    for (int o = 16; o; o >>= 1) {
        a0 += __shfl_down_sync(0xffffffffu, a0, o);
        a1 += __shfl_down_sync(0xffffffffu, a1, o);
        a2 += __shfl_down_sync(0xffffffffu, a2, o);
        a3 += __shfl_down_sync(0xffffffffu, a3, o);
        a4 += __shfl_down_sync(0xffffffffu, a4, o);
        a5 += __shfl_down_sync(0xffffffffu, a5, o);
    }
    if (lane == 0) {
        float4 spv;
        spv.x = fminf(fmaxf(a0 + b_fs[0], -100.f), 100.f);
        spv.y = fminf(fmaxf(a1 + b_fs[1], -100.f), 100.f);
        spv.z = fminf(fmaxf(a2 + b_fs[2], -100.f), 100.f);
        spv.w = fminf(fmaxf(a3 + b_fs[3], -100.f), 100.f);
        float it0 = fmaxf(a4 + b_fc[0], 0.f);
        float it1 = fmaxf(a5 + b_fc[1], 0.f);
        *(float4*)&out[((size_t)b * TDEC + t) * 4] = spv;
        *(float4*)&g_ls[b * 4] = spv;
        float4 lpv;
        lpv.x = fmaxf(W_emb[0] * it0 + W_emb[1] * it1 + b_emb[0], 0.f);
        lpv.y = fmaxf(W_emb[2] * it0 + W_emb[3] * it1 + b_emb[1], 0.f);
        lpv.z = fmaxf(W_emb[4] * it0 + W_emb[5] * it1 + b_emb[2], 0.f);
        lpv.w = fmaxf(W_emb[6] * it0 + W_emb[7] * it1 + b_emb[3], 0.f);
        *(float4*)&g_lp[b * 4] = lpv;
        if (t == TDEC - 1) {
            float mx = fmaxf(it0, it1);
            float e0 = expf(it0 - mx), e1 = expf(it1 - mx);
            float s = e0 + e1;
            out[(size_t)BATCH * TDEC * 4 + b * 2]     = e0 / s;
            out[(size_t)BATCH * TDEC * 4 + b * 2 + 1] = e1 / s;
        }
    }
}

// ---------------- launch ----------------
extern "C" void kernel_launch(void* const* d_in, const int* in_sizes, int n_in,
                              void* d_out, int out_size)
{
    const float* speed = (const float*)d_in[0];
    const float* pos   = (const float*)d_in[1];
    WPtrs wpt;
    wpt.Wi[0] = (const float*)d_in[2];  wpt.Wh[0] = (const float*)d_in[3];  wpt.bb[0] = (const float*)d_in[4];
    wpt.Wi[1] = (const float*)d_in[5];  wpt.Wh[1] = (const float*)d_in[6];  wpt.bb[1] = (const float*)d_in[7];
    wpt.Wi[2] = (const float*)d_in[8];  wpt.Wh[2] = (const float*)d_in[9];  wpt.bb[2] = (const float*)d_in[10];
    wpt.Wi[3] = (const float*)d_in[11]; wpt.Wh[3] = (const float*)d_in[12]; wpt.bb[3] = (const float*)d_in[13];
    const float* W_fs  = (const float*)d_in[14];
    const float* b_fs  = (const float*)d_in[15];
    const float* W_fc  = (const float*)d_in[16];
    const float* b_fc  = (const float*)d_in[17];
    const float* W_emb = (const float*)d_in[18];
    const float* b_emb = (const float*)d_in[19];
    float* out = (float*)d_out;

    cudaFuncSetAttribute(lstm_cell, cudaFuncAttributeMaxDynamicSharedMemorySize, DYN_SMEM);

    prep_weights<<<dim3(NG, 4), 512>>>(wpt);
    init_state<<<(2 * BATCH * H + 255) / 256, 256>>>(speed, pos);

    dim3 cgrid(NG / BN, BATCH / BM, 2);   // (16, 32, 2)
    for (int t = 0; t < OBS; t++)
        lstm_cell<<<cgrid, THREADS, DYN_SMEM>>>(0, speed + t * 4, pos + t * 4, OBS * 4, 0,
                                                t & 1, t == OBS - 1 ? 1 : 0);

    combine_state<<<(BATCH * H + 255) / 256, 256>>>();

    for (int t = 0; t < TDEC; t++) {
        lstm_cell<<<cgrid, THREADS, DYN_SMEM>>>(2, nullptr, nullptr, 4, 1, t & 1, 0);
        proj_kernel<<<BATCH / 32, 1024>>>(W_fs, b_fs, W_fc, b_fc, W_emb, b_emb, out, t, 1 - (t & 1));
    }
}